// round 12
// baseline (speedup 1.0000x reference)
#include <cuda_runtime.h>

// CTC loss. One 512-thread CTA per batch element (grid=128 -> 1 CTA/SM):
//   w0 = forward compute (alpha, t=1..tm), w1 = backward compute (gamma,
//   t=len-1..tm+1), w2-8 = fwd loaders, w9-15 = bwd loaders.
// Extended-range u*2^E arithmetic, block-rebased every RSTEPS=8 steps.
// Loaders: static-indexed LDG pipeline (DEPTH=6), exp on gathered states,
// monotone per-loader progress counters (st.release/ld.acquire), pure-spin
// backpressure (no nanosleep). Halves combine in shared memory.

#define NST    5
#define RSTEPS 8
#define RD     32          // ring rows per direction (power of 2)
#define LEAD   20          // loader lead bound (< RD - 8)
#define DEPTH  6           // loader LDG pipeline depth (static stages)
#define NLD    7           // loader warps per direction
#define SENT   (-(1 << 28))

#define RING_B   (RD * NST * 32 * 4)
#define SCR_B    (2 * NLD * 256 * 4)
#define SMEM_TOT (2 * RING_B + SCR_B + 4 * (2 * NLD + 2 + 4 * NST * 32 + 16 + 1) + 64)

__device__ float    g_loss[1024];
__device__ unsigned g_cnt = 0;

__device__ __forceinline__ void st_release_cta(int* p, int v) {
    asm volatile("st.release.cta.b32 [%0], %1;" :: "l"(p), "r"(v) : "memory");
}
__device__ __forceinline__ int ld_acquire_cta(const int* p) {
    int v;
    asm volatile("ld.acquire.cta.b32 %0, [%1];" : "=r"(v) : "l"(p) : "memory");
    return v;
}
__device__ __forceinline__ int iclamp(int x, int lo, int hi) {
    return min(max(x, lo), hi);
}
__device__ __forceinline__ float mkscale(int d) {
    return __int_as_float((d + 127) << 23);
}

__device__ __forceinline__ void loader_warp(
    const float* src, size_t BC,
    int t_begin, int cnt, int stride, int lo, int hi,
    float (*ring)[NST * 32], int* progP,
    volatile int* consP, int consSign,
    float* scratch, const int* lab2, int lane)
{
    float4 Aa[DEPTH], Ab[DEPTH];
    int tq = t_begin;
#pragma unroll
    for (int k = 0; k < DEPTH; ++k) {
        int tt = iclamp(tq, lo, hi);
        const float* r = src + (size_t)tt * BC;
        Aa[k] = *(const float4*)r;
        Ab[k] = *(const float4*)(r + 4);
        tq += stride;
    }
    int t = t_begin;
    int consv = *consP;
    const int c0 = lane * 8;
    while (cnt > 0) {
#pragma unroll
        for (int k = 0; k < DEPTH; ++k) {
            if (cnt > 0) {
                for (;;) {                         // pure-spin backpressure
                    int lead = (consSign > 0) ? (t - consv) : (consv - t);
                    if (lead < LEAD) break;
                    consv = *consP;
                }
                float* scr = scratch + c0;
                ((float4*)scr)[0] = Aa[k];
                ((float4*)scr)[1] = Ab[k];
                __syncwarp();
                float* dst = ring[t & (RD - 1)];
#pragma unroll
                for (int j = 0; j < NST; ++j)
                    dst[j * 32 + lane] = __expf(scratch[lab2[j]]);
                __syncwarp();
                if (lane == 0) st_release_cta(progP, t);
                int tt = iclamp(tq, lo, hi);
                const float* r = src + (size_t)tt * BC;
                Aa[k] = *(const float4*)r;
                Ab[k] = *(const float4*)(r + 4);
                tq += stride;
                t += stride;
                --cnt;
            }
        }
    }
    __syncwarp();
    if (lane == 0)
        st_release_cta(progP, (consSign > 0) ? 0x3fffffff : -0x3fffffff);
}

__global__ void __launch_bounds__(512, 1)
ctc_merged_kernel(const float* __restrict__ logp,
                  const int*   __restrict__ targets,
                  const int*   __restrict__ in_len,
                  const int*   __restrict__ tgt_len,
                  float*       __restrict__ out,
                  int T, int B, int C, int S)
{
    const int b    = blockIdx.x;
    const int tid  = threadIdx.x;
    const int w    = tid >> 5;
    const int lane = tid & 31;
    const int L    = 2 * S + 1;
    const int* tgt = targets + (size_t)b * S;

    extern __shared__ __align__(16) char dsm[];
    float (*ringF)[NST * 32] = (float(*)[NST * 32])(dsm);
    float (*ringB)[NST * 32] = (float(*)[NST * 32])(dsm + RING_B);
    float (*scrA)[256]       = (float(*)[256])(dsm + 2 * RING_B);
    int*  progF = (int*)(dsm + 2 * RING_B + SCR_B);
    int*  progB = progF + NLD;
    volatile int* consF = (volatile int*)(progB + NLD);
    volatile int* consB = consF + 1;
    float* fvF = (float*)(progB + NLD + 2);
    int*   feF = (int*)(fvF + NST * 32);
    float* fvB = (float*)(feF + NST * 32);
    int*   feB = (int*)(fvB + NST * 32);
    float* red = (float*)(feB + NST * 32);
    int*   s_last = (int*)(red + 16);

    const size_t BC   = (size_t)B * C;
    const float* base = logp + (size_t)b * C;

    int len = in_len[b];
    if (len > T) len = T;
    if (len < 1) len = 1;
    const int lenm1 = len - 1;
    const int tm    = lenm1 >> 1;
    const int tmp1  = tm + 1;
    const bool use_gamma = (lenm1 > tm);

    if (tid == 0) { *consF = 0; *consB = len; *s_last = 0; }
    if (tid < NLD)          progF[tid] = 0;
    else if (tid < 2 * NLD) progB[tid - NLD] = len + 8;
    __syncthreads();

    if (w == 0) {
        // ================= forward compute (alpha) =================
        int skm[NST];
#pragma unroll
        for (int j = 0; j < NST; ++j) {
            int s = lane * NST + j;
            int sk = 0;
            if (s < L && s >= 3 && (s & 1)) {
                int lab = tgt[s >> 1];
                int lm2 = tgt[(s - 2) >> 1];
                if (lab != 0 && lab != lm2) sk = 1;
            }
            skm[j] = sk;
        }
        float u[NST]; int Eb[NST];
#pragma unroll
        for (int j = 0; j < NST; ++j) { u[j] = 0.0f; Eb[j] = SENT; }
        if (lane == 0) {
            float y0 = __ldg(base) * 1.4426950408889634f;
            float f0 = floorf(y0); Eb[0] = (int)f0; u[0] = exp2f(y0 - f0);
            if (L > 1) {
                int lab1 = tgt[0];
                float y1 = __ldg(base + lab1) * 1.4426950408889634f;
                float f1 = floorf(y1); Eb[1] = (int)f1; u[1] = exp2f(y1 - f1);
            }
        }

        int mn = 0;
        for (int t0 = 1; t0 <= tm; t0 += RSTEPS) {
            int tend = t0 + RSTEPS - 1; if (tend > tm) tend = tm;
            if (mn < tend) {
                do {
                    mn = ld_acquire_cta(&progF[0]);
#pragma unroll
                    for (int q = 1; q < NLD; ++q)
                        mn = min(mn, ld_acquire_cta(&progF[q]));
                } while (mn < tend);
            }
            float P[RSTEPS][NST];
#pragma unroll
            for (int k = 0; k < RSTEPS; ++k) {
                int t = t0 + k; if (t > tm) t = tm;
                const float* rp = &ringF[t & (RD - 1)][0];
#pragma unroll
                for (int j = 0; j < NST; ++j) P[k][j] = rp[j * 32 + lane];
            }
            // rebase: E'[s] = max(Et[s-16..s])
            int Et[NST], mb[NST];
#pragma unroll
            for (int j = 0; j < NST; ++j) {
                int bits = __float_as_int(u[j]);
                int ex   = (bits >> 23) & 0xff;
                Et[j] = (ex == 0) ? SENT : (Eb[j] + ex - 127);
                mb[j] = bits & 0x007fffff;
            }
            int P0 = Et[0];
            int P1 = max(P0, Et[1]);
            int P2 = max(P1, Et[2]);
            int P3 = max(P2, Et[3]);
            int P4 = max(P3, Et[4]);
            int S4 = Et[4];
            int S3 = max(Et[3], S4);
            int S2 = max(Et[2], S3);
            int S1 = max(Et[1], S2);
            int Mm1  = __shfl_up_sync(0xffffffffu, P4, 1);    if (lane < 1) Mm1  = SENT;
            int Mm2  = __shfl_up_sync(0xffffffffu, P4, 2);    if (lane < 2) Mm2  = SENT;
            int Mm3  = __shfl_up_sync(0xffffffffu, P4, 3);    if (lane < 3) Mm3  = SENT;
            int S1m3 = __shfl_up_sync(0xffffffffu, S1, 3);    if (lane < 3) S1m3 = SENT;
            int S2m3 = __shfl_up_sync(0xffffffffu, S2, 3);    if (lane < 3) S2m3 = SENT;
            int S3m3 = __shfl_up_sync(0xffffffffu, S3, 3);    if (lane < 3) S3m3 = SENT;
            int E4m4 = __shfl_up_sync(0xffffffffu, Et[4], 4); if (lane < 4) E4m4 = SENT;
            int M12 = max(Mm1, Mm2);
            int E0 = max(max(P0, M12), max(Mm3, E4m4));
            int E1 = max(max(P1, M12), Mm3);
            int E2 = max(max(P2, M12), S1m3);
            int E3 = max(max(P3, M12), S2m3);
            int E4 = max(max(P4, M12), S3m3);
            int En[NST] = {E0, E1, E2, E3, E4};
#pragma unroll
            for (int j = 0; j < NST; ++j) {
                int d = Et[j] - En[j];
                u[j] = (d < -126 || Et[j] <= SENT) ? 0.0f
                     : __int_as_float(mb[j] | ((d + 127) << 23));
            }
            int E4m1 = __shfl_up_sync(0xffffffffu, E4, 1); if (lane < 1) E4m1 = SENT;
            int E3m1 = __shfl_up_sync(0xffffffffu, E3, 1); if (lane < 1) E3m1 = SENT;
            int Em1[NST] = {E4m1, E0, E1, E2, E3};
            int Em2[NST] = {E3m1, E4m1, E0, E1, E2};
            float sb[NST], sc[NST];
#pragma unroll
            for (int j = 0; j < NST; ++j) {
                int db = min(Em1[j] - En[j], 126);
                sb[j] = (db < -126 || Em1[j] <= SENT) ? 0.0f : mkscale(db);
                int dc = min(Em2[j] - En[j], 126);
                float scv = (dc < -126 || Em2[j] <= SENT) ? 0.0f : mkscale(dc);
                sc[j] = skm[j] ? scv : 0.0f;
                Eb[j] = En[j];
            }
#pragma unroll
            for (int k = 0; k < RSTEPS; ++k) {
                int t = t0 + k;
                if (t <= tm) {
                    float vm1 = __shfl_up_sync(0xffffffffu, u[4], 1);
                    float vm2 = __shfl_up_sync(0xffffffffu, u[3], 1);
                    if (lane == 0) { vm1 = 0.0f; vm2 = 0.0f; }
                    float n0 = fmaf(vm2,  sc[0], fmaf(vm1,  sb[0], u[0])) * P[k][0];
                    float n1 = fmaf(vm1,  sc[1], fmaf(u[0], sb[1], u[1])) * P[k][1];
                    float n2 = fmaf(u[0], sc[2], fmaf(u[1], sb[2], u[2])) * P[k][2];
                    float n3 = fmaf(u[1], sc[3], fmaf(u[2], sb[3], u[3])) * P[k][3];
                    float n4 = fmaf(u[2], sc[4], fmaf(u[3], sb[4], u[4])) * P[k][4];
                    u[0] = n0; u[1] = n1; u[2] = n2; u[3] = n3; u[4] = n4;
                }
            }
            if (lane == 0) *consF = tend;
        }
#pragma unroll
        for (int j = 0; j < NST; ++j) {
            int bits = __float_as_int(u[j]);
            int ex   = (bits >> 23) & 0xff;
            feF[lane * NST + j] = (ex == 0) ? SENT : (Eb[j] + ex - 127);
            fvF[lane * NST + j] = (ex == 0) ? 0.0f
                                : __int_as_float((bits & 0x007fffff) | 0x3f800000);
        }
    } else if (w == 1) {
        // ================= backward compute (gamma) =================
        int sk2m[NST];
#pragma unroll
        for (int j = 0; j < NST; ++j) {
            int s = lane * NST + j;
            int sk = 0;
            if ((s & 1) && (s + 2 <= L - 1)) {
                int lab  = tgt[s >> 1];
                int labp = tgt[(s >> 1) + 1];
                if (labp != 0 && labp != lab) sk = 1;
            }
            sk2m[j] = sk;
        }
        float u[NST]; int Eb[NST];
#pragma unroll
        for (int j = 0; j < NST; ++j) { u[j] = 0.0f; Eb[j] = SENT; }

        if (use_gamma) {
            int tl = tgt_len[b];
            int hi = 2 * tl; if (hi > L - 1) hi = L - 1;
            {
                int mx;
                do {
                    mx = ld_acquire_cta(&progB[0]);
#pragma unroll
                    for (int q = 1; q < NLD; ++q)
                        mx = max(mx, ld_acquire_cta(&progB[q]));
                } while (mx > lenm1);
                const float* rp = &ringB[lenm1 & (RD - 1)][0];
#pragma unroll
                for (int j = 0; j < NST; ++j) {
                    int s = lane * NST + j;
                    if (tl > 0 && (s == hi || s == hi - 1)) {
                        u[j]  = rp[j * 32 + lane];
                        Eb[j] = 0;
                    }
                }
                if (lane == 0) *consB = lenm1;
            }
            int mx = lenm1;
            for (int t0 = lenm1 - 1; t0 >= tmp1; t0 -= RSTEPS) {
                int tlow = t0 - RSTEPS + 1; if (tlow < tmp1) tlow = tmp1;
                if (mx > tlow) {
                    do {
                        mx = ld_acquire_cta(&progB[0]);
#pragma unroll
                        for (int q = 1; q < NLD; ++q)
                            mx = max(mx, ld_acquire_cta(&progB[q]));
                    } while (mx > tlow);
                }
                float P[RSTEPS][NST];
#pragma unroll
                for (int k = 0; k < RSTEPS; ++k) {
                    int t = t0 - k; if (t < tmp1) t = tmp1;
                    const float* rp = &ringB[t & (RD - 1)][0];
#pragma unroll
                    for (int j = 0; j < NST; ++j) P[k][j] = rp[j * 32 + lane];
                }
                // rebase: E'[s] = max(Et[s..s+16])
                int Et[NST], mb[NST];
#pragma unroll
                for (int j = 0; j < NST; ++j) {
                    int bits = __float_as_int(u[j]);
                    int ex   = (bits >> 23) & 0xff;
                    Et[j] = (ex == 0) ? SENT : (Eb[j] + ex - 127);
                    mb[j] = bits & 0x007fffff;
                }
                int Pm1 = max(Et[0], Et[1]);
                int Pm2 = max(Pm1, Et[2]);
                int Pm3 = max(Pm2, Et[3]);
                int M   = max(Pm3, Et[4]);
                int Sm4 = Et[4];
                int Sm3 = max(Et[3], Sm4);
                int Sm2 = max(Et[2], Sm3);
                int Sm1 = max(Et[1], Sm2);
                int Sm0 = max(Et[0], Sm1);
                int Mp1  = __shfl_down_sync(0xffffffffu, M, 1);     if (lane > 30) Mp1  = SENT;
                int Mp2  = __shfl_down_sync(0xffffffffu, M, 2);     if (lane > 29) Mp2  = SENT;
                int Mp3  = __shfl_down_sync(0xffffffffu, M, 3);     if (lane > 28) Mp3  = SENT;
                int P1p3 = __shfl_down_sync(0xffffffffu, Pm1, 3);   if (lane > 28) P1p3 = SENT;
                int P2p3 = __shfl_down_sync(0xffffffffu, Pm2, 3);   if (lane > 28) P2p3 = SENT;
                int P3p3 = __shfl_down_sync(0xffffffffu, Pm3, 3);   if (lane > 28) P3p3 = SENT;
                int E0p4 = __shfl_down_sync(0xffffffffu, Et[0], 4); if (lane > 27) E0p4 = SENT;
                int M12 = max(Mp1, Mp2);
                int E0 = max(max(Sm0, M12), P1p3);
                int E1 = max(max(Sm1, M12), P2p3);
                int E2 = max(max(Sm2, M12), P3p3);
                int E3 = max(max(Sm3, M12), Mp3);
                int E4 = max(max(Sm4, M12), max(Mp3, E0p4));
                int En[NST] = {E0, E1, E2, E3, E4};
#pragma unroll
                for (int j = 0; j < NST; ++j) {
                    int d = Et[j] - En[j];
                    u[j] = (d < -126 || Et[j] <= SENT) ? 0.0f
                         : __int_as_float(mb[j] | ((d + 127) << 23));
                }
                int E0p1 = __shfl_down_sync(0xffffffffu, E0, 1); if (lane > 30) E0p1 = SENT;
                int E1p1 = __shfl_down_sync(0xffffffffu, E1, 1); if (lane > 30) E1p1 = SENT;
                int Ep1[NST] = {E1, E2, E3, E4, E0p1};
                int Ep2[NST] = {E2, E3, E4, E0p1, E1p1};
                float sb[NST], sc[NST];
#pragma unroll
                for (int j = 0; j < NST; ++j) {
                    int db = min(Ep1[j] - En[j], 126);
                    sb[j] = (db < -126 || Ep1[j] <= SENT) ? 0.0f : mkscale(db);
                    int dc = min(Ep2[j] - En[j], 126);
                    float scv = (dc < -126 || Ep2[j] <= SENT) ? 0.0f : mkscale(dc);
                    sc[j] = sk2m[j] ? scv : 0.0f;
                    Eb[j] = En[j];
                }
#pragma unroll
                for (int k = 0; k < RSTEPS; ++k) {
                    int t = t0 - k;
                    if (t >= tmp1) {
                        float d0 = __shfl_down_sync(0xffffffffu, u[0], 1);
                        float d1 = __shfl_down_sync(0xffffffffu, u[1], 1);
                        if (lane == 31) { d0 = 0.0f; d1 = 0.0f; }
                        float n0 = fmaf(u[2], sc[0], fmaf(u[1], sb[0], u[0])) * P[k][0];
                        float n1 = fmaf(u[3], sc[1], fmaf(u[2], sb[1], u[1])) * P[k][1];
                        float n2 = fmaf(u[4], sc[2], fmaf(u[3], sb[2], u[2])) * P[k][2];
                        float n3 = fmaf(d0,   sc[3], fmaf(u[4], sb[3], u[3])) * P[k][3];
                        float n4 = fmaf(d1,   sc[4], fmaf(d0,   sb[4], u[4])) * P[k][4];
                        u[0] = n0; u[1] = n1; u[2] = n2; u[3] = n3; u[4] = n4;
                    }
                }
                if (lane == 0) *consB = tlow;
            }
        }
#pragma unroll
        for (int j = 0; j < NST; ++j) {
            int bits = __float_as_int(u[j]);
            int ex   = (bits >> 23) & 0xff;
            feB[lane * NST + j] = (ex == 0) ? SENT : (Eb[j] + ex - 127);
            fvB[lane * NST + j] = (ex == 0) ? 0.0f
                                : __int_as_float((bits & 0x007fffff) | 0x3f800000);
        }
    } else {
        // ================= loader warps (w = 2..15) =================
        int lab2[NST];
#pragma unroll
        for (int j = 0; j < NST; ++j) {
            int s = lane * NST + j;
            int lab = 0;
            if (s < L && (s & 1)) lab = tgt[s >> 1];
            lab2[j] = lab;
        }
        const float* src = base + lane * 8;
        int i = w - 2;                               // 0..13
        if (i < NLD) {
            int cnt = (tm >= 1 + i) ? ((tm - 1 - i) / NLD + 1) : 0;
            loader_warp(src, BC, 1 + i, cnt, NLD, 1, max(tm, 1),
                        ringF, &progF[i], consF, +1, &scrA[i][0], lab2, lane);
        } else {
            i -= NLD;
            int start = lenm1 - i;
            int cnt = (start >= tmp1) ? ((start - tmp1) / NLD + 1) : 0;
            int lo = min(tmp1, lenm1); if (lo < 0) lo = 0;
            loader_warp(src, BC, start, cnt, -NLD, lo, lenm1,
                        ringB, &progB[i], consB, -1, &scrA[NLD + i][0], lab2, lane);
        }
    }
    __syncthreads();

    // ================= combine: ll = sum_s alpha_tm[s] * beta_tm[s] =======
    if (w == 0) {
        int tl = tgt_len[b];
        int hi = 2 * tl; if (hi > L - 1) hi = L - 1;
        float Tv[NST]; int Te[NST];
#pragma unroll
        for (int j = 0; j < NST; ++j) { Tv[j] = 0.0f; Te[j] = SENT; }
        if (tl > 0) {
#pragma unroll
            for (int j = 0; j < NST; ++j) {
                int s = lane * NST + j;
                if (s < L) {
                    float va = fvF[s]; int ea = feF[s];
                    if (va != 0.0f) {
                        if (use_gamma) {
                            float g0v = fvB[s];     int g0e = feB[s];
                            float g1v = 0.0f;       int g1e = SENT;
                            float g2v = 0.0f;       int g2e = SENT;
                            if (s + 1 <= L - 1) { g1v = fvB[s + 1]; g1e = feB[s + 1]; }
                            int sk2 = 0;
                            if ((s & 1) && (s + 2 <= L - 1)) {
                                int lab  = tgt[s >> 1];
                                int labp = tgt[(s >> 1) + 1];
                                if (labp != 0 && labp != lab) sk2 = 1;
                            }
                            if (sk2) { g2v = fvB[s + 2]; g2e = feB[s + 2]; }
                            if (g0v == 0.0f) g0e = SENT;
                            if (g1v == 0.0f) g1e = SENT;
                            if (g2v == 0.0f) g2e = SENT;
                            int m = max(g0e, max(g1e, g2e));
                            if (m > SENT / 2) {
                                float bsum = 0.0f;
                                if (g0e > SENT / 2 && g0e - m >= -126) bsum += g0v * mkscale(g0e - m);
                                if (g1e > SENT / 2 && g1e - m >= -126) bsum += g1v * mkscale(g1e - m);
                                if (g2e > SENT / 2 && g2e - m >= -126) bsum += g2v * mkscale(g2e - m);
                                if (bsum > 0.0f) { Tv[j] = va * bsum; Te[j] = ea + m; }
                            }
                        } else {
                            if (s == hi || s == hi - 1) { Tv[j] = va; Te[j] = ea; }
                        }
                    }
                }
            }
        }
        int M = SENT;
#pragma unroll
        for (int j = 0; j < NST; ++j) if (Tv[j] > 0.0f) M = max(M, Te[j]);
#pragma unroll
        for (int o = 16; o > 0; o >>= 1)
            M = max(M, __shfl_xor_sync(0xffffffffu, M, o));
        double acc = 0.0;
#pragma unroll
        for (int j = 0; j < NST; ++j) {
            if (Tv[j] > 0.0f) {
                long long d = (long long)Te[j] - M;
                if (d > -1000) {
                    unsigned long long bits2 = (unsigned long long)(d + 1023) << 52;
                    acc += (double)Tv[j] * __longlong_as_double((long long)bits2);
                }
            }
        }
#pragma unroll
        for (int o = 16; o > 0; o >>= 1)
            acc += __shfl_xor_sync(0xffffffffu, acc, o);
        if (lane == 0) {
            float loss = 0.0f;
            if (tl > 0 && acc > 0.0 && M > SENT / 2) {
                double ll = ((double)M + log2(acc)) * 0.69314718055994530942;
                loss = (float)(-ll / (double)tl);
            }
            g_loss[b] = loss;
            __threadfence();
            unsigned old = atomicAdd(&g_cnt, 1);
            if (old == (unsigned)(gridDim.x - 1)) *s_last = 1;
        }
    }
    __syncthreads();

    // ---- last CTA: fused mean reduction ----
    if (*s_last) {
        __threadfence();
        float acc2 = 0.0f;
        for (int i2 = tid; i2 < B; i2 += 512) acc2 += g_loss[i2];
#pragma unroll
        for (int o = 16; o > 0; o >>= 1)
            acc2 += __shfl_xor_sync(0xffffffffu, acc2, o);
        if (lane == 0) red[w] = acc2;
        __syncthreads();
        if (tid == 0) {
            float s16 = 0.0f;
#pragma unroll
            for (int k = 0; k < 16; ++k) s16 += red[k];
            out[0] = s16 / (float)B;
            g_cnt = 0;   // reset for next graph replay
        }
    }
}

extern "C" void kernel_launch(void* const* d_in, const int* in_sizes, int n_in,
                              void* d_out, int out_size)
{
    const float* logp    = (const float*)d_in[0];
    const int*   targets = (const int*)d_in[1];
    const int*   in_len  = (const int*)d_in[2];
    const int*   tgt_len = (const int*)d_in[3];

    int B = in_sizes[2];                                   // 128
    int S = in_sizes[1] / B;                               // 64
    int C = 256;
    int T = (int)((size_t)in_sizes[0] / ((size_t)B * C));  // 1024

    cudaFuncSetAttribute(ctc_merged_kernel,
                         cudaFuncAttributeMaxDynamicSharedMemorySize, SMEM_TOT);
    ctc_merged_kernel<<<B, 512, SMEM_TOT>>>(logp, targets, in_len, tgt_len,
                                            (float*)d_out, T, B, C, S);
}